// round 8
// baseline (speedup 1.0000x reference)
#include <cuda_runtime.h>
#include <cuda_fp16.h>

#define B_   8
#define H_   8
#define QS_  64
#define KS_  512
#define A_   64
#define DH_  64
#define KC_  64
#define NP_  8      // chunks == partials per (b,h)
#define QD_  512
#define KD_  512

typedef unsigned long long ull;

__device__ float g_pout[B_*H_*NP_*QS_*DH_];   // 8 MB
__device__ float g_Sx[B_*H_*NP_*QS_];
__device__ int   g_cnt[B_*H_];                // zero-init; self-resetting

__device__ __forceinline__ float fast_tanh(float v) {
    float y; asm("tanh.approx.f32 %0, %1;" : "=f"(y) : "f"(v)); return y;
}
__device__ __forceinline__ ull pk2(float x, float y) {
    ull r; asm("mov.b64 %0, {%1, %2};" : "=l"(r) : "f"(x), "f"(y)); return r;
}
__device__ __forceinline__ float2 upk2(ull v) {
    float2 r; asm("mov.b64 {%0, %1}, %2;" : "=f"(r.x), "=f"(r.y) : "l"(v)); return r;
}
__device__ __forceinline__ ull ffma2(ull a, ull b, ull c) {
    ull d; asm("fma.rn.f32x2 %0, %1, %2, %3;" : "=l"(d) : "l"(a), "l"(b), "l"(c)); return d;
}

// ---------------- smem layout (bytes), total 53824 -> 4 CTAs/SM ----------------
//  s_xv   @0      f32[64][68] 17408   (query in ph1; x chunk (=K=V) after; V until end)
//  s_kph  @17408  half[64][72] 9216   ([a][k])
//  s_qph  @26624  half[64][72] 9216   ([a][q])
//  s_Wst  @35840  f32[64][68] 17408   (Wq, then Wk, then p f32[64][68])
//  s_misc @53248  bias f32[64]; w2 f32[64] @53504; flag int @53760
#define SMF_BYTES 53824

// 64 rows x 64 a projection GEMM: s_in[r*68+d], s_w[a*68+d] -> s_out[a*72+r] (half)
__device__ __forceinline__ void proj_gemm(
    const float* __restrict__ s_in, const float* __restrict__ s_w,
    __half* __restrict__ s_out, const float* __restrict__ s_bias,
    int tx, int ty)
{
    ull acc2[4][4];
#pragma unroll
    for (int i = 0; i < 4; i++)
#pragma unroll
        for (int j = 0; j < 4; j++) acc2[i][j] = 0ULL;

#pragma unroll
    for (int d4 = 0; d4 < 16; d4++) {
        ull wv[4][2];
#pragma unroll
        for (int j = 0; j < 4; j++) {
            float4 v = *(const float4*)&s_w[(tx + 16 * j) * 68 + d4 * 4];
            wv[j][0] = pk2(v.x, v.y); wv[j][1] = pk2(v.z, v.w);
        }
#pragma unroll
        for (int i = 0; i < 4; i++) {
            float4 v = *(const float4*)&s_in[(ty * 4 + i) * 68 + d4 * 4];
            ull r0 = pk2(v.x, v.y), r1 = pk2(v.z, v.w);
#pragma unroll
            for (int j = 0; j < 4; j++) {
                acc2[i][j] = ffma2(r0, wv[j][0], acc2[i][j]);
                acc2[i][j] = ffma2(r1, wv[j][1], acc2[i][j]);
            }
        }
    }
#pragma unroll
    for (int i = 0; i < 4; i++)
#pragma unroll
        for (int j = 0; j < 4; j++) {
            float2 p = upk2(acc2[i][j]);
            float v = p.x + p.y + (s_bias ? s_bias[tx + 16 * j] : 0.f);
            s_out[(tx + 16 * j) * 72 + ty * 4 + i] = __float2half_rn(v);
        }
}

__global__ void __launch_bounds__(256, 4) fused_kernel(
    const float* __restrict__ x, const float* __restrict__ query,
    const float* __restrict__ W, const float* __restrict__ bias,
    const float* __restrict__ w2, const unsigned char* __restrict__ mask,
    float* __restrict__ out)
{
    extern __shared__ char sm[];
    float*  s_xv  = (float*)(sm);
    __half* s_kph = (__half*)(sm + 17408);
    __half* s_qph = (__half*)(sm + 26624);
    float*  s_Wst = (float*)(sm + 35840);
    float*  s_p   = (float*)(sm + 35840);      // aliases s_Wst after kp GEMM
    float*  s_bias= (float*)(sm + 53248);
    float*  s_w2  = (float*)(sm + 53504);
    int*    s_last= (int*)(sm + 53760);

    const int kc = blockIdx.x, h = blockIdx.y, b = blockIdx.z;
    const int tid = threadIdx.x;
    const int tx = tid & 15, ty = tid >> 4;
    const int warp = tid >> 5, lane = tid & 31;
    const int bh = b * H_ + h;

    if (tid < 64) { s_bias[tid] = bias[tid]; s_w2[tid] = w2[tid]; }

    // ---- phase 1: stage query + Wq ----
#pragma unroll
    for (int i = 0; i < 4; i++) {
        int idx = tid + 256 * i; int q = idx >> 4, d4 = idx & 15;
        *(float4*)&s_xv[q * 68 + d4 * 4] =
            *(const float4*)&query[(size_t)(b * QS_ + q) * QD_ + h * DH_ + d4 * 4];
    }
#pragma unroll
    for (int i = 0; i < 4; i++) {
        int idx = tid + 256 * i; int a = idx >> 4, d4 = idx & 15;
        *(float4*)&s_Wst[a * 68 + d4 * 4] = *(const float4*)&W[a * 128 + 64 + d4 * 4];
    }
    __syncthreads();

    // ---- qp projection -> s_qph[a][q] ----
    proj_gemm(s_xv, s_Wst, s_qph, s_bias, tx, ty);
    __syncthreads();

    // ---- phase 2: stage x chunk (K=V) over query + Wk over Wq ----
#pragma unroll
    for (int i = 0; i < 4; i++) {
        int idx = tid + 256 * i; int k = idx >> 4, d4 = idx & 15;
        *(float4*)&s_xv[k * 68 + d4 * 4] =
            *(const float4*)&x[((size_t)b * KS_ + kc * KC_ + k) * KD_ + h * DH_ + d4 * 4];
    }
#pragma unroll
    for (int i = 0; i < 4; i++) {
        int idx = tid + 256 * i; int a = idx >> 4, d4 = idx & 15;
        *(float4*)&s_Wst[a * 68 + d4 * 4] = *(const float4*)&W[a * 128 + d4 * 4];
    }
    __syncthreads();

    // ---- kp projection -> s_kph[a][k] ----
    proj_gemm(s_xv, s_Wst, s_kph, (const float*)0, tx, ty);
    __syncthreads();   // LAST CTA-wide barrier before the merge phase

    // ---- phase 3: tanh scores + exp (no max; |score| <= sum|w2| ~ 2.6) ----
    //      thread: q rows q0=ty*4 (+4), k cols k0=tx*4 (+4)
    //      warp w covers q rows 8w..8w+7 -> p is warp-local
    const int q0 = ty * 4, k0 = tx * 4;
    float acc[4][4];
#pragma unroll
    for (int j = 0; j < 4; j++)
#pragma unroll
        for (int i = 0; i < 4; i++) acc[j][i] = 0.f;

#pragma unroll 4
    for (int a = 0; a < A_; a++) {
        uint2 qr = *(const uint2*)&s_qph[a * 72 + q0];
        uint2 kr = *(const uint2*)&s_kph[a * 72 + k0];
        float2 qf0 = __half22float2(((const __half2*)&qr)[0]);
        float2 qf1 = __half22float2(((const __half2*)&qr)[1]);
        float2 kf0 = __half22float2(((const __half2*)&kr)[0]);
        float2 kf1 = __half22float2(((const __half2*)&kr)[1]);
        float w2a = s_w2[a];
        float qs[4] = {qf0.x, qf0.y, qf1.x, qf1.y};
        float ks[4] = {kf0.x, kf0.y, kf1.x, kf1.y};
#pragma unroll
        for (int j = 0; j < 4; j++)
#pragma unroll
            for (int i = 0; i < 4; i++)
                acc[j][i] += w2a * fast_tanh(qs[j] + ks[i]);
    }

    float rowsum[4];
    {
        uchar4 mk4 = *(const uchar4*)&mask[b * KS_ + kc * KC_ + k0];
        unsigned char mk[4] = {mk4.x, mk4.y, mk4.z, mk4.w};
#pragma unroll
        for (int j = 0; j < 4; j++) {
            float s = 0.f;
#pragma unroll
            for (int i = 0; i < 4; i++) {
                float p = mk[i] ? 0.f : __expf(acc[j][i]);
                acc[j][i] = p;
                s += p;
            }
            // sum over the 16 lanes covering all k for this row
#pragma unroll
            for (int o = 8; o; o >>= 1) s += __shfl_xor_sync(0xffffffffu, s, o);
            rowsum[j] = s;
        }
        // write unnormalized p over the (dead) Wk region — warp-local rows
#pragma unroll
        for (int j = 0; j < 4; j++)
            *(float4*)&s_p[(q0 + j) * 68 + k0] =
                make_float4(acc[j][0], acc[j][1], acc[j][2], acc[j][3]);
    }
    __syncwarp();   // p rows for this warp are complete; no CTA barrier needed

    // ---- phase 4: pV, warp-local (warp w: q rows 8w..8w+7, all 64 d) ----
    {
        const int dg = lane & 7;          // d0 = 8*dg
        const int qg = lane >> 3;         // 2 rows: qa, qa+1
        const int d0 = dg * 8;
        const int qa = warp * 8 + qg * 2;
        ull oA[4], oB[4];
#pragma unroll
        for (int c = 0; c < 4; c++) { oA[c] = 0ULL; oB[c] = 0ULL; }

#pragma unroll 4
        for (int k = 0; k < KC_; k++) {
            float4 v0 = *(float4*)&s_xv[k * 68 + d0];
            float4 v1 = *(float4*)&s_xv[k * 68 + d0 + 4];
            ull w0 = pk2(v0.x, v0.y), w1 = pk2(v0.z, v0.w);
            ull w2v = pk2(v1.x, v1.y), w3 = pk2(v1.z, v1.w);
            float pA = s_p[qa * 68 + k];
            float pB = s_p[(qa + 1) * 68 + k];
            ull pA2 = pk2(pA, pA), pB2 = pk2(pB, pB);
            oA[0] = ffma2(pA2, w0, oA[0]); oA[1] = ffma2(pA2, w1, oA[1]);
            oA[2] = ffma2(pA2, w2v, oA[2]); oA[3] = ffma2(pA2, w3, oA[3]);
            oB[0] = ffma2(pB2, w0, oB[0]); oB[1] = ffma2(pB2, w1, oB[1]);
            oB[2] = ffma2(pB2, w2v, oB[2]); oB[3] = ffma2(pB2, w3, oB[3]);
        }

        const int pp = bh * NP_ + kc;
        {
            float2 a0 = upk2(oA[0]), a1 = upk2(oA[1]), a2 = upk2(oA[2]), a3 = upk2(oA[3]);
            *(float4*)&g_pout[(size_t)(pp * QS_ + qa) * DH_ + d0]     = make_float4(a0.x, a0.y, a1.x, a1.y);
            *(float4*)&g_pout[(size_t)(pp * QS_ + qa) * DH_ + d0 + 4] = make_float4(a2.x, a2.y, a3.x, a3.y);
            float2 b0 = upk2(oB[0]), b1 = upk2(oB[1]), b2 = upk2(oB[2]), b3 = upk2(oB[3]);
            *(float4*)&g_pout[(size_t)(pp * QS_ + qa + 1) * DH_ + d0]     = make_float4(b0.x, b0.y, b1.x, b1.y);
            *(float4*)&g_pout[(size_t)(pp * QS_ + qa + 1) * DH_ + d0 + 4] = make_float4(b2.x, b2.y, b3.x, b3.y);
        }
        if (tx == 0) {   // lanes 0 and 16 of each warp: rows q0..q0+3
#pragma unroll
            for (int j = 0; j < 4; j++)
                g_Sx[pp * QS_ + q0 + j] = rowsum[j];
        }
    }

    // ---- last CTA per (b,h) merges the 8 partials ----
    __threadfence();
    __syncthreads();
    if (tid == 0) {
        int old = atomicAdd(&g_cnt[bh], 1);
        *s_last = (old == NP_ - 1);
    }
    __syncthreads();
    if (*s_last) {
        __threadfence();
        const int qrow = tid >> 2, l4 = tid & 3;
        float St = 0.f;
#pragma unroll
        for (int p = 0; p < NP_; p++) St += g_Sx[(bh * NP_ + p) * QS_ + qrow];
        float inv = 1.f / St;
#pragma unroll
        for (int j = 0; j < 4; j++) {
            int dd = l4 * 16 + j * 4;
            float4 a = make_float4(0.f, 0.f, 0.f, 0.f);
#pragma unroll
            for (int p = 0; p < NP_; p++) {
                float4 v = *(const float4*)&g_pout[(size_t)((bh * NP_ + p) * QS_ + qrow) * DH_ + dd];
                a.x += v.x; a.y += v.y; a.z += v.z; a.w += v.w;
            }
            a.x *= inv; a.y *= inv; a.z *= inv; a.w *= inv;
            *(float4*)&out[(size_t)(b * QS_ + qrow) * QD_ + h * DH_ + dd] = a;
        }
        if (tid == 0) g_cnt[bh] = 0;   // reset for next graph replay
    }
}

// ---------------- launch ----------------
extern "C" void kernel_launch(void* const* d_in, const int* in_sizes, int n_in,
                              void* d_out, int out_size) {
    const float* x     = (const float*)d_in[0];
    const float* query = (const float*)d_in[1];
    const float* W     = (const float*)d_in[2];
    const float* bias  = (const float*)d_in[3];
    const float* w2    = (const float*)d_in[4];
    const unsigned char* mask = (const unsigned char*)d_in[5];
    float* out = (float*)d_out;

    cudaFuncSetAttribute(fused_kernel, cudaFuncAttributeMaxDynamicSharedMemorySize, SMF_BYTES);

    fused_kernel<<<dim3(NP_, H_, B_), 256, SMF_BYTES>>>(x, query, W, bias, w2, mask, out);
}

// round 9
// speedup vs baseline: 1.2774x; 1.2774x over previous
#include <cuda_runtime.h>
#include <cuda_fp16.h>

#define B_   8
#define H_   8
#define QS_  64
#define KS_  512
#define A_   64
#define DH_  64
#define KC_  128
#define NP_  4      // chunks == partials per (b,h)
#define QD_  512
#define KD_  512

typedef unsigned long long ull;

__device__ float g_pout[B_*H_*NP_*QS_*DH_];   // 4 MB
__device__ float g_Sx[B_*H_*NP_*QS_];
__device__ int   g_cnt[B_*H_];                // zero-init; self-resetting

__device__ __forceinline__ float fast_tanh(float v) {
    float y; asm("tanh.approx.f32 %0, %1;" : "=f"(y) : "f"(v)); return y;
}
__device__ __forceinline__ ull pk2(float x, float y) {
    ull r; asm("mov.b64 %0, {%1, %2};" : "=l"(r) : "f"(x), "f"(y)); return r;
}
__device__ __forceinline__ float2 upk2(ull v) {
    float2 r; asm("mov.b64 {%0, %1}, %2;" : "=f"(r.x), "=f"(r.y) : "l"(v)); return r;
}
__device__ __forceinline__ ull ffma2(ull a, ull b, ull c) {
    ull d; asm("fma.rn.f32x2 %0, %1, %2, %3;" : "=l"(d) : "l"(a), "l"(b), "l"(c)); return d;
}

// ---------------- smem layout (bytes), total 113216 -> 2 CTAs/SM ----------------
//  OFF_Q    0       f32[64][68]  query   (dead after qp GEMM)
//  OFF_W    17408   f32[64][68]  Wq, then Wk (dead after kp GEMM)
//  OFF_P    0       f32[64][132] p       (aliases Q+W after kp GEMM)
//  OFF_XV   34816   f32[128][68] x chunk == K == V (staged at t0, persists)
//  OFF_QPH  69632   half[64][72] qp [a][q]
//  OFF_KP   78848   f32[64][132] kp [a][k]
//  OFF_BIAS 112640, OFF_W2 112896, OFF_LAST 113152
#define SMF_BYTES 113216

__global__ void __launch_bounds__(256, 2) fused_kernel(
    const float* __restrict__ x, const float* __restrict__ query,
    const float* __restrict__ W, const float* __restrict__ bias,
    const float* __restrict__ w2, const unsigned char* __restrict__ mask,
    float* __restrict__ out)
{
    extern __shared__ char sm[];
    float*  s_q   = (float*)(sm);
    float*  s_W   = (float*)(sm + 17408);
    float*  s_p   = (float*)(sm);
    float*  s_xv  = (float*)(sm + 34816);
    __half* s_qph = (__half*)(sm + 69632);
    float*  s_kp  = (float*)(sm + 78848);
    float*  s_bias= (float*)(sm + 112640);
    float*  s_w2  = (float*)(sm + 112896);
    int*    s_last= (int*)(sm + 113152);

    const int kc = blockIdx.x, h = blockIdx.y, b = blockIdx.z;
    const int tid = threadIdx.x;
    const int tx = tid & 15, ty = tid >> 4;
    const int bh = b * H_ + h;

    if (tid < 64) { s_bias[tid] = bias[tid]; s_w2[tid] = w2[tid]; }

    // ---- t0: stage query + Wq + x chunk (x into its own buffer, overlaps) ----
#pragma unroll
    for (int i = 0; i < 4; i++) {
        int idx = tid + 256 * i; int q = idx >> 4, d4 = idx & 15;
        *(float4*)&s_q[q * 68 + d4 * 4] =
            *(const float4*)&query[(size_t)(b * QS_ + q) * QD_ + h * DH_ + d4 * 4];
    }
#pragma unroll
    for (int i = 0; i < 4; i++) {
        int idx = tid + 256 * i; int a = idx >> 4, d4 = idx & 15;
        *(float4*)&s_W[a * 68 + d4 * 4] = *(const float4*)&W[a * 128 + 64 + d4 * 4];
    }
#pragma unroll
    for (int i = 0; i < 8; i++) {
        int idx = tid + 256 * i; int k = idx >> 4, d4 = idx & 15;
        *(float4*)&s_xv[k * 68 + d4 * 4] =
            *(const float4*)&x[((size_t)b * KS_ + kc * KC_ + k) * KD_ + h * DH_ + d4 * 4];
    }
    __syncthreads();

    // ---- qp GEMM (f32x2): q rows ty*4+i, a cols tx+16j -> s_qph[a][q] (half) ----
    {
        ull acc2[4][4];
#pragma unroll
        for (int i = 0; i < 4; i++)
#pragma unroll
            for (int j = 0; j < 4; j++) acc2[i][j] = 0ULL;
#pragma unroll
        for (int d4 = 0; d4 < 16; d4++) {
            ull wv[4][2];
#pragma unroll
            for (int j = 0; j < 4; j++) {
                float4 v = *(float4*)&s_W[(tx + 16 * j) * 68 + d4 * 4];
                wv[j][0] = pk2(v.x, v.y); wv[j][1] = pk2(v.z, v.w);
            }
#pragma unroll
            for (int i = 0; i < 4; i++) {
                float4 v = *(float4*)&s_q[(ty * 4 + i) * 68 + d4 * 4];
                ull r0 = pk2(v.x, v.y), r1 = pk2(v.z, v.w);
#pragma unroll
                for (int j = 0; j < 4; j++) {
                    acc2[i][j] = ffma2(r0, wv[j][0], acc2[i][j]);
                    acc2[i][j] = ffma2(r1, wv[j][1], acc2[i][j]);
                }
            }
        }
#pragma unroll
        for (int i = 0; i < 4; i++)
#pragma unroll
            for (int j = 0; j < 4; j++) {
                float2 p = upk2(acc2[i][j]);
                float v = p.x + p.y + s_bias[tx + 16 * j];
                s_qph[(tx + 16 * j) * 72 + ty * 4 + i] = __float2half_rn(v);
            }
    }
    __syncthreads();

    // ---- stage Wk over Wq ----
#pragma unroll
    for (int i = 0; i < 4; i++) {
        int idx = tid + 256 * i; int a = idx >> 4, d4 = idx & 15;
        *(float4*)&s_W[a * 68 + d4 * 4] = *(const float4*)&W[a * 128 + d4 * 4];
    }
    __syncthreads();

    // ---- kp GEMM (f32x2): k rows ty*8+i (128), a cols tx+16j -> s_kp[a][k] f32 ----
    {
        ull acc2[8][4];
#pragma unroll
        for (int i = 0; i < 8; i++)
#pragma unroll
            for (int j = 0; j < 4; j++) acc2[i][j] = 0ULL;
#pragma unroll
        for (int d4 = 0; d4 < 16; d4++) {
            ull wv[4][2];
#pragma unroll
            for (int j = 0; j < 4; j++) {
                float4 v = *(float4*)&s_W[(tx + 16 * j) * 68 + d4 * 4];
                wv[j][0] = pk2(v.x, v.y); wv[j][1] = pk2(v.z, v.w);
            }
#pragma unroll
            for (int i = 0; i < 8; i++) {
                float4 v = *(float4*)&s_xv[(ty * 8 + i) * 68 + d4 * 4];
                ull r0 = pk2(v.x, v.y), r1 = pk2(v.z, v.w);
#pragma unroll
                for (int j = 0; j < 4; j++) {
                    acc2[i][j] = ffma2(r0, wv[j][0], acc2[i][j]);
                    acc2[i][j] = ffma2(r1, wv[j][1], acc2[i][j]);
                }
            }
        }
#pragma unroll
        for (int i = 0; i < 8; i++)
#pragma unroll
            for (int j = 0; j < 4; j++) {
                float2 p = upk2(acc2[i][j]);
                s_kp[(tx + 16 * j) * 132 + ty * 8 + i] = p.x + p.y;
            }
    }
    __syncthreads();   // last CTA-wide barrier before merge phase

    // ---- tanh scores + exp (no max; |score| <= sum|w2| ~ 2.6) ----
    //      q rows q0=ty*4 (4), k cols k0=tx*8 (8); warp w owns q rows 8w..8w+7
    const int q0 = ty * 4, k0 = tx * 8;
    float acc[4][8];
#pragma unroll
    for (int j = 0; j < 4; j++)
#pragma unroll
        for (int i = 0; i < 8; i++) acc[j][i] = 0.f;

#pragma unroll 4
    for (int a = 0; a < A_; a++) {
        uint2 qhu = *(const uint2*)&s_qph[a * 72 + q0];
        float2 qf0 = __half22float2(((const __half2*)&qhu)[0]);
        float2 qf1 = __half22float2(((const __half2*)&qhu)[1]);
        float4 kA = *(float4*)&s_kp[a * 132 + k0];
        float4 kB = *(float4*)&s_kp[a * 132 + k0 + 4];
        float w2a = s_w2[a];
        float qs[4] = {qf0.x, qf0.y, qf1.x, qf1.y};
        float ks[8] = {kA.x, kA.y, kA.z, kA.w, kB.x, kB.y, kB.z, kB.w};
#pragma unroll
        for (int j = 0; j < 4; j++)
#pragma unroll
            for (int i = 0; i < 8; i++)
                acc[j][i] += w2a * fast_tanh(qs[j] + ks[i]);
    }

    float rowsum[4];
    {
        unsigned char mk[8];
        const unsigned char* mrow = &mask[b * KS_ + kc * KC_ + k0];
#pragma unroll
        for (int i = 0; i < 8; i++) mk[i] = mrow[i];
#pragma unroll
        for (int j = 0; j < 4; j++) {
            float s = 0.f;
#pragma unroll
            for (int i = 0; i < 8; i++) {
                float p = mk[i] ? 0.f : __expf(acc[j][i]);
                acc[j][i] = p;
                s += p;
            }
#pragma unroll
            for (int o = 8; o; o >>= 1) s += __shfl_xor_sync(0xffffffffu, s, o);
            rowsum[j] = s;
        }
        // p over the dead Q+W region — rows are warp-local
#pragma unroll
        for (int j = 0; j < 4; j++) {
            *(float4*)&s_p[(q0 + j) * 132 + k0]     = make_float4(acc[j][0], acc[j][1], acc[j][2], acc[j][3]);
            *(float4*)&s_p[(q0 + j) * 132 + k0 + 4] = make_float4(acc[j][4], acc[j][5], acc[j][6], acc[j][7]);
        }
    }
    __syncwarp();   // pV below reads only this warp's p rows

    // ---- pV (4q x 4d per thread over 128 k), V = s_xv ----
    {
        const int txd = tid & 15, tyq = tid >> 4;
        const int d0 = txd * 4, q0b = tyq * 4;
        ull o2[4][2];
#pragma unroll
        for (int j = 0; j < 4; j++) { o2[j][0] = 0ULL; o2[j][1] = 0ULL; }

#pragma unroll 4
        for (int k = 0; k < KC_; k++) {
            float4 v = *(float4*)&s_xv[k * 68 + d0];
            ull v0 = pk2(v.x, v.y), v1 = pk2(v.z, v.w);
#pragma unroll
            for (int j = 0; j < 4; j++) {
                float p = s_p[(q0b + j) * 132 + k];
                ull p2 = pk2(p, p);
                o2[j][0] = ffma2(p2, v0, o2[j][0]);
                o2[j][1] = ffma2(p2, v1, o2[j][1]);
            }
        }

        const int pp = bh * NP_ + kc;
#pragma unroll
        for (int j = 0; j < 4; j++) {
            float2 a0 = upk2(o2[j][0]), a1 = upk2(o2[j][1]);
            *(float4*)&g_pout[(size_t)(pp * QS_ + q0b + j) * DH_ + d0] =
                make_float4(a0.x, a0.y, a1.x, a1.y);
        }
        if (tx == 0) {
#pragma unroll
            for (int j = 0; j < 4; j++)
                g_Sx[pp * QS_ + q0 + j] = rowsum[j];
        }
    }

    // ---- last CTA per (b,h) merges the NP_ partials ----
    __threadfence();
    __syncthreads();
    if (tid == 0) {
        int old = atomicAdd(&g_cnt[bh], 1);
        *s_last = (old == NP_ - 1);
    }
    __syncthreads();
    if (*s_last) {
        __threadfence();
        const int qrow = tid >> 2, l4 = tid & 3;
        float St = 0.f;
#pragma unroll
        for (int p = 0; p < NP_; p++) St += g_Sx[(bh * NP_ + p) * QS_ + qrow];
        float inv = 1.f / St;
#pragma unroll
        for (int j = 0; j < 4; j++) {
            int dd = l4 * 16 + j * 4;
            float4 a = make_float4(0.f, 0.f, 0.f, 0.f);
#pragma unroll
            for (int p = 0; p < NP_; p++) {
                float4 v = *(const float4*)&g_pout[(size_t)((bh * NP_ + p) * QS_ + qrow) * DH_ + dd];
                a.x += v.x; a.y += v.y; a.z += v.z; a.w += v.w;
            }
            a.x *= inv; a.y *= inv; a.z *= inv; a.w *= inv;
            *(float4*)&out[(size_t)(b * QS_ + qrow) * QD_ + h * DH_ + dd] = a;
        }
        if (tid == 0) g_cnt[bh] = 0;   // reset for next graph replay
    }
}

// ---------------- launch ----------------
extern "C" void kernel_launch(void* const* d_in, const int* in_sizes, int n_in,
                              void* d_out, int out_size) {
    const float* x     = (const float*)d_in[0];
    const float* query = (const float*)d_in[1];
    const float* W     = (const float*)d_in[2];
    const float* bias  = (const float*)d_in[3];
    const float* w2    = (const float*)d_in[4];
    const unsigned char* mask = (const unsigned char*)d_in[5];
    float* out = (float*)d_out;

    cudaFuncSetAttribute(fused_kernel, cudaFuncAttributeMaxDynamicSharedMemorySize, SMF_BYTES);

    fused_kernel<<<dim3(NP_, H_, B_), 256, SMF_BYTES>>>(x, query, W, bias, w2, mask, out);
}

// round 11
// speedup vs baseline: 1.2953x; 1.0140x over previous
#include <cuda_runtime.h>

#define B_  8
#define H_  8
#define QS_ 64
#define KS_ 512
#define A_  64
#define DH_ 64
#define KC_ 128
#define NC_ 4
#define QD_ 512
#define KD_ 512
#define NF_ 32   // a in [0,NF): FMA-pipe reciprocal path; a in [NF,64): MUFU tanh path

typedef unsigned long long ull;

__device__ float g_pout[B_*H_*NC_*QS_*DH_];   // 4 MB
__device__ float g_Sx[B_*H_*NC_*QS_];

__device__ __forceinline__ float fast_tanh(float v) {
    float y; asm("tanh.approx.f32 %0, %1;" : "=f"(y) : "f"(v)); return y;
}
__device__ __forceinline__ ull pk2(float x, float y) {
    ull r; asm("mov.b64 %0, {%1, %2};" : "=l"(r) : "f"(x), "f"(y)); return r;
}
__device__ __forceinline__ float2 upk2(ull v) {
    float2 r; asm("mov.b64 {%0, %1}, %2;" : "=f"(r.x), "=f"(r.y) : "l"(v)); return r;
}
__device__ __forceinline__ ull ffma2(ull a, ull b, ull c) {
    ull d; asm("fma.rn.f32x2 %0, %1, %2, %3;" : "=l"(d) : "l"(a), "l"(b), "l"(c)); return d;
}
// packed fast-reciprocal seed for 1/v given nv = -v (v >= 1):
// seed_int = 0x7EF311C3 - asint(v) = 0xFEF311C3 - asint(nv)  (mod 2^32)
__device__ __forceinline__ ull rcp_seed2(ull nv) {
    unsigned lo, hi;
    asm("mov.b64 {%0, %1}, %2;" : "=r"(lo), "=r"(hi) : "l"(nv));
    lo = 0xFEF311C3u - lo;
    hi = 0xFEF311C3u - hi;
    ull r; asm("mov.b64 %0, {%1, %2};" : "=l"(r) : "r"(lo), "r"(hi));
    return r;
}

// ---------------- smem layout (bytes) — R5 layout, verbatim ----------------
// s_xv @0 f32[128][68]; s_q @34816 f32[64][64] (STRIDE 64 — ends 51200);
// s_W1 @51200 f32[64][68]; s_kp @34816 (alias, f32[64][132]);
// s_Wk @68608; s_p @68608 (alias); s_qp @86016 f32[64][68];
// s_bias @103424; s_w2 @103680
#define SMF_BYTES 103936

__global__ void __launch_bounds__(256, 2) fused_kernel(
    const float* __restrict__ x, const float* __restrict__ query,
    const float* __restrict__ W, const float* __restrict__ bias,
    const float* __restrict__ w2, const unsigned char* __restrict__ mask)
{
    extern __shared__ char sm[];
    float* s_xv  = (float*)(sm);
    float* s_q   = (float*)(sm + 34816);
    float* s_W1  = (float*)(sm + 51200);
    float* s_kp  = (float*)(sm + 34816);
    float* s_Wk  = (float*)(sm + 68608);
    float* s_p   = (float*)(sm + 68608);
    float* s_qp  = (float*)(sm + 86016);
    float* s_bias= (float*)(sm + 103424);
    float* s_w2  = (float*)(sm + 103680);

    const int kc = blockIdx.x, h = blockIdx.y, b = blockIdx.z;
    const int tid = threadIdx.x;
    const int tx = tid & 15, ty = tid >> 4;
    const int bh = b * H_ + h;
    const float LOG2E2 = 2.885390082f;   // 2*log2(e), for e^{2v} = 2^{v*2log2e}

    if (tid < 64) { s_bias[tid] = bias[tid]; s_w2[tid] = w2[tid]; }

    // ---- phase 1: stage query [64][64] (stride 64!) + Wq ----
#pragma unroll
    for (int i = 0; i < 4; i++) {
        int idx = tid + 256 * i; int q = idx >> 4, d4 = idx & 15;
        *(float4*)&s_q[q * 64 + d4 * 4] =
            *(const float4*)&query[(size_t)(b * QS_ + q) * QD_ + h * DH_ + d4 * 4];
    }
#pragma unroll
    for (int i = 0; i < 4; i++) {
        int idx = tid + 256 * i; int a = idx >> 4, d4 = idx & 15;
        *(float4*)&s_W1[a * 68 + d4 * 4] = *(const float4*)&W[a * 128 + 64 + d4 * 4];
    }
    __syncthreads();

    // ---- qp GEMM (f32x2) -> s_qp[a][q]; a<NF stored as e^{2*qp} ----
    {
        ull acc2[4][4];
#pragma unroll
        for (int i = 0; i < 4; i++)
#pragma unroll
            for (int j = 0; j < 4; j++) acc2[i][j] = 0ULL;
#pragma unroll
        for (int d4 = 0; d4 < 16; d4++) {
            ull wv[4][2];
#pragma unroll
            for (int j = 0; j < 4; j++) {
                float4 v = *(float4*)&s_W1[(tx + 16 * j) * 68 + d4 * 4];
                wv[j][0] = pk2(v.x, v.y); wv[j][1] = pk2(v.z, v.w);
            }
#pragma unroll
            for (int i = 0; i < 4; i++) {
                float4 v = *(float4*)&s_q[(ty * 4 + i) * 64 + d4 * 4];
                ull r0 = pk2(v.x, v.y), r1 = pk2(v.z, v.w);
#pragma unroll
                for (int j = 0; j < 4; j++) {
                    acc2[i][j] = ffma2(r0, wv[j][0], acc2[i][j]);
                    acc2[i][j] = ffma2(r1, wv[j][1], acc2[i][j]);
                }
            }
        }
#pragma unroll
        for (int i = 0; i < 4; i++)
#pragma unroll
            for (int j = 0; j < 4; j++) {
                float2 p = upk2(acc2[i][j]);
                float v = p.x + p.y + s_bias[tx + 16 * j];
                if (j < 2) v = exp2f(v * LOG2E2);          // Eq = e^{2*qp}, a<32
                s_qp[(tx + 16 * j) * 68 + ty * 4 + i] = v;
            }
    }
    __syncthreads();

    // ---- phase 2: stage x chunk [128][68] + Wk ----
#pragma unroll
    for (int i = 0; i < 8; i++) {
        int idx = tid + 256 * i; int k = idx >> 4, d4 = idx & 15;
        *(float4*)&s_xv[k * 68 + d4 * 4] =
            *(const float4*)&x[((size_t)b * KS_ + kc * KC_ + k) * KD_ + h * DH_ + d4 * 4];
    }
#pragma unroll
    for (int i = 0; i < 4; i++) {
        int idx = tid + 256 * i; int a = idx >> 4, d4 = idx & 15;
        *(float4*)&s_Wk[a * 68 + d4 * 4] = *(const float4*)&W[a * 128 + d4 * 4];
    }
    __syncthreads();

    // ---- kp GEMM (f32x2) -> s_kp[a][k]; a<NF stored as -e^{2*kp} ----
    {
        ull acc2[8][4];
#pragma unroll
        for (int i = 0; i < 8; i++)
#pragma unroll
            for (int j = 0; j < 4; j++) acc2[i][j] = 0ULL;
#pragma unroll
        for (int d4 = 0; d4 < 16; d4++) {
            ull wv[4][2];
#pragma unroll
            for (int j = 0; j < 4; j++) {
                float4 v = *(float4*)&s_Wk[(tx + 16 * j) * 68 + d4 * 4];
                wv[j][0] = pk2(v.x, v.y); wv[j][1] = pk2(v.z, v.w);
            }
#pragma unroll
            for (int i = 0; i < 8; i++) {
                float4 v = *(float4*)&s_xv[(ty * 8 + i) * 68 + d4 * 4];
                ull r0 = pk2(v.x, v.y), r1 = pk2(v.z, v.w);
#pragma unroll
                for (int j = 0; j < 4; j++) {
                    acc2[i][j] = ffma2(r0, wv[j][0], acc2[i][j]);
                    acc2[i][j] = ffma2(r1, wv[j][1], acc2[i][j]);
                }
            }
        }
#pragma unroll
        for (int i = 0; i < 8; i++)
#pragma unroll
            for (int j = 0; j < 4; j++) {
                float2 p = upk2(acc2[i][j]);
                float v = p.x + p.y;
                if (j < 2) v = -exp2f(v * LOG2E2);         // Ekn = -e^{2*kp}, a<32
                s_kp[(tx + 16 * j) * 132 + ty * 8 + i] = v;
            }
    }
    __syncthreads();

    // ---- phase 3: scores. q rows q0=ty*4 (4), k cols k0=tx*8 (8) ----
    const int q0 = ty * 4, k0 = tx * 8;
    const ull NEG1_2 = pk2(-1.f, -1.f);
    const ull ONE_2  = pk2(1.f, 1.f);

    // C = sum_{a<NF} w2[a], folded into accumulator init
    float C = 0.f;
#pragma unroll
    for (int a4 = 0; a4 < NF_ / 4; a4++) {
        float4 wv4 = *(float4*)&s_w2[a4 * 4];
        C += wv4.x + wv4.y + wv4.z + wv4.w;
    }

    ull acc2[4][4];
#pragma unroll
    for (int j = 0; j < 4; j++)
#pragma unroll
        for (int i = 0; i < 4; i++) acc2[j][i] = pk2(C, C);

    // -- FMA-pipe path: a in [0,NF): tanh = 1 - 2/(Eq*Ek + 1), Newton rcp --
#pragma unroll 4
    for (int a = 0; a < NF_; a++) {
        float4 eq  = *(float4*)&s_qp[a * 68 + q0];
        float4 ekA = *(float4*)&s_kp[a * 132 + k0];
        float4 ekB = *(float4*)&s_kp[a * 132 + k0 + 4];
        ull ek[4] = {pk2(ekA.x, ekA.y), pk2(ekA.z, ekA.w),
                     pk2(ekB.x, ekB.y), pk2(ekB.z, ekB.w)};
        float w2m = -2.f * s_w2[a];
        ull w22 = pk2(w2m, w2m);
        float eqs[4] = {eq.x, eq.y, eq.z, eq.w};
#pragma unroll
        for (int j = 0; j < 4; j++) {
            ull eqj = pk2(eqs[j], eqs[j]);
#pragma unroll
            for (int i = 0; i < 4; i++) {
                ull nv = ffma2(eqj, ek[i], NEG1_2);     // -(Eq*Ek + 1)
                ull r  = rcp_seed2(nv);
                ull e  = ffma2(nv, r, ONE_2);           // 1 - v*r
                r = ffma2(r, e, r);                      // r*(2 - v*r)
                e = ffma2(nv, r, ONE_2);
                r = ffma2(r, e, r);
                acc2[j][i] = ffma2(w22, r, acc2[j][i]);  // += w2a*(1-2r) (C prefolded)
            }
        }
    }

    // unpack to scalars for the MUFU path
    float acc[4][8];
#pragma unroll
    for (int j = 0; j < 4; j++)
#pragma unroll
        for (int i = 0; i < 4; i++) {
            float2 f = upk2(acc2[j][i]);
            acc[j][2 * i] = f.x; acc[j][2 * i + 1] = f.y;
        }

    // -- MUFU path: a in [NF,64): direct tanh.approx --
#pragma unroll 4
    for (int a = NF_; a < A_; a++) {
        float4 qv = *(float4*)&s_qp[a * 68 + q0];
        float4 kA = *(float4*)&s_kp[a * 132 + k0];
        float4 kB = *(float4*)&s_kp[a * 132 + k0 + 4];
        float w2a = s_w2[a];
        float qs[4] = {qv.x, qv.y, qv.z, qv.w};
        float ks[8] = {kA.x, kA.y, kA.z, kA.w, kB.x, kB.y, kB.z, kB.w};
#pragma unroll
        for (int j = 0; j < 4; j++)
#pragma unroll
            for (int i = 0; i < 8; i++)
                acc[j][i] += w2a * fast_tanh(qs[j] + ks[i]);
    }

    // ---- phase 4: exp (no max; |score| <= sum|w2|), rowsum, p to smem ----
    float rowsum[4];
    {
        unsigned char mk[8];
        const unsigned char* mrow = &mask[b * KS_ + kc * KC_ + k0];
#pragma unroll
        for (int i = 0; i < 8; i++) mk[i] = mrow[i];
#pragma unroll
        for (int j = 0; j < 4; j++) {
            float s = 0.f;
#pragma unroll
            for (int i = 0; i < 8; i++) {
                float p = mk[i] ? 0.f : __expf(acc[j][i]);
                acc[j][i] = p;
                s += p;
            }
#pragma unroll
            for (int o = 8; o; o >>= 1) s += __shfl_xor_sync(0xffffffffu, s, o);
            rowsum[j] = s;
        }
    }
    __syncthreads();   // phase-3 reads done before p overwrites Wk/qp region

#pragma unroll
    for (int j = 0; j < 4; j++) {
        *(float4*)&s_p[(q0 + j) * 132 + k0]     = make_float4(acc[j][0], acc[j][1], acc[j][2], acc[j][3]);
        *(float4*)&s_p[(q0 + j) * 132 + k0 + 4] = make_float4(acc[j][4], acc[j][5], acc[j][6], acc[j][7]);
    }
    if (tx == 0) {
#pragma unroll
        for (int j = 0; j < 4; j++)
            g_Sx[(bh * NC_ + kc) * QS_ + q0 + j] = rowsum[j];
    }
    __syncthreads();

    // ---- phase 5: partial out = p @ V (4q x 4d per thread) ----
    {
        const int txd = tid & 15, tyq = tid >> 4;
        const int d0 = txd * 4, q0b = tyq * 4;
        ull o2[4][2];
#pragma unroll
        for (int j = 0; j < 4; j++) { o2[j][0] = 0ULL; o2[j][1] = 0ULL; }

#pragma unroll 4
        for (int k = 0; k < KC_; k++) {
            float4 v = *(float4*)&s_xv[k * 68 + d0];
            ull v0 = pk2(v.x, v.y), v1 = pk2(v.z, v.w);
#pragma unroll
            for (int j = 0; j < 4; j++) {
                float p = s_p[(q0b + j) * 132 + k];
                ull p2 = pk2(p, p);
                o2[j][0] = ffma2(p2, v0, o2[j][0]);
                o2[j][1] = ffma2(p2, v1, o2[j][1]);
            }
        }
#pragma unroll
        for (int j = 0; j < 4; j++) {
            float2 a0 = upk2(o2[j][0]), a1 = upk2(o2[j][1]);
            *(float4*)&g_pout[(size_t)((bh * NC_ + kc) * QS_ + q0b + j) * DH_ + d0] =
                make_float4(a0.x, a0.y, a1.x, a1.y);
        }
    }
}

// ---------------- combine: merge 4 chunk partials, 1 float4 per thread ----------------
__global__ void __launch_bounds__(256) combine_kernel(float* __restrict__ out)
{
    const int idx = blockIdx.x * 256 + threadIdx.x;   // 0..1023 per bh
    const int bh = blockIdx.y;
    const int b = bh >> 3, h = bh & 7;
    const int q = idx >> 4, d0 = (idx & 15) * 4;

    float S = 0.f;
#pragma unroll
    for (int c = 0; c < NC_; c++) S += g_Sx[(bh * NC_ + c) * QS_ + q];
    float inv = 1.f / S;

    float4 a = make_float4(0.f, 0.f, 0.f, 0.f);
#pragma unroll
    for (int c = 0; c < NC_; c++) {
        float4 v = *(const float4*)&g_pout[(size_t)((bh * NC_ + c) * QS_ + q) * DH_ + d0];
        a.x += v.x; a.y += v.y; a.z += v.z; a.w += v.w;
    }
    a.x *= inv; a.y *= inv; a.z *= inv; a.w *= inv;

    *(float4*)&out[(size_t)(b * QS_ + q) * QD_ + h * DH_ + d0] = a;
}

// ---------------- launch ----------------
extern "C" void kernel_launch(void* const* d_in, const int* in_sizes, int n_in,
                              void* d_out, int out_size) {
    const float* x     = (const float*)d_in[0];
    const float* query = (const float*)d_in[1];
    const float* W     = (const float*)d_in[2];
    const float* bias  = (const float*)d_in[3];
    const float* w2    = (const float*)d_in[4];
    const unsigned char* mask = (const unsigned char*)d_in[5];
    float* out = (float*)d_out;

    cudaFuncSetAttribute(fused_kernel, cudaFuncAttributeMaxDynamicSharedMemorySize, SMF_BYTES);

    fused_kernel<<<dim3(NC_, H_, B_), 256, SMF_BYTES>>>(x, query, W, bias, w2, mask);
    combine_kernel<<<dim3(4, B_ * H_), 256>>>(out);
}

// round 12
// speedup vs baseline: 1.4767x; 1.1400x over previous
#include <cuda_runtime.h>

#define B_  8
#define H_  8
#define QS_ 64
#define KS_ 512
#define A_  64
#define DH_ 64
#define KC_ 128
#define NC_ 4
#define QD_ 512
#define KD_ 512
#define NF_ 32   // a in [0,NF): FMA-pipe reciprocal path; a in [NF,64): MUFU tanh path

typedef unsigned long long ull;

__device__ float g_pout[B_*H_*NC_*QS_*DH_];   // 4 MB
__device__ float g_Sx[B_*H_*NC_*QS_];

__device__ __forceinline__ float fast_tanh(float v) {
    float y; asm("tanh.approx.f32 %0, %1;" : "=f"(y) : "f"(v)); return y;
}
__device__ __forceinline__ ull pk2(float x, float y) {
    ull r; asm("mov.b64 %0, {%1, %2};" : "=l"(r) : "f"(x), "f"(y)); return r;
}
__device__ __forceinline__ float2 upk2(ull v) {
    float2 r; asm("mov.b64 {%0, %1}, %2;" : "=f"(r.x), "=f"(r.y) : "l"(v)); return r;
}
__device__ __forceinline__ ull ffma2(ull a, ull b, ull c) {
    ull d; asm("fma.rn.f32x2 %0, %1, %2, %3;" : "=l"(d) : "l"(a), "l"(b), "l"(c)); return d;
}
// packed fast-reciprocal seed for 1/v given nv = -v (v >= 1):
// seed_int = 0x7EF311C3 - asint(v) = 0xFEF311C3 - asint(nv)  (mod 2^32)
__device__ __forceinline__ ull rcp_seed2(ull nv) {
    unsigned lo, hi;
    asm("mov.b64 {%0, %1}, %2;" : "=r"(lo), "=r"(hi) : "l"(nv));
    lo = 0xFEF311C3u - lo;
    hi = 0xFEF311C3u - hi;
    ull r; asm("mov.b64 %0, {%1, %2};" : "=l"(r) : "r"(lo), "r"(hi));
    return r;
}

// ---------------- smem layout (bytes) — R11 layout, verbatim ----------------
// s_xv @0 f32[128][68]; s_q @34816 f32[64][64] (stride 64, ends 51200);
// s_W1 @51200 f32[64][68]; s_kp @34816 (alias, f32[64][132]);
// s_Wk @68608; s_p @68608 (alias); s_qp @86016 f32[64][68];
// s_bias @103424; s_w2 @103680
#define SMF_BYTES 103936

__global__ void __launch_bounds__(256, 2) fused_kernel(
    const float* __restrict__ x, const float* __restrict__ query,
    const float* __restrict__ W, const float* __restrict__ bias,
    const float* __restrict__ w2, const unsigned char* __restrict__ mask)
{
    extern __shared__ char sm[];
    float* s_xv  = (float*)(sm);
    float* s_q   = (float*)(sm + 34816);
    float* s_W1  = (float*)(sm + 51200);
    float* s_kp  = (float*)(sm + 34816);
    float* s_Wk  = (float*)(sm + 68608);
    float* s_p   = (float*)(sm + 68608);
    float* s_qp  = (float*)(sm + 86016);
    float* s_bias= (float*)(sm + 103424);
    float* s_w2  = (float*)(sm + 103680);

    const int kc = blockIdx.x, h = blockIdx.y, b = blockIdx.z;
    const int tid = threadIdx.x;
    const int tx = tid & 15, ty = tid >> 4;
    const int bh = b * H_ + h;
    const float LOG2E2 = 2.885390082f;   // 2*log2(e), for e^{2v} = 2^{v*2log2e}

    if (tid < 64) { s_bias[tid] = bias[tid]; s_w2[tid] = w2[tid]; }

    // ---- phase 1: stage query [64][64] (stride 64) + Wq ----
#pragma unroll
    for (int i = 0; i < 4; i++) {
        int idx = tid + 256 * i; int q = idx >> 4, d4 = idx & 15;
        *(float4*)&s_q[q * 64 + d4 * 4] =
            *(const float4*)&query[(size_t)(b * QS_ + q) * QD_ + h * DH_ + d4 * 4];
    }
#pragma unroll
    for (int i = 0; i < 4; i++) {
        int idx = tid + 256 * i; int a = idx >> 4, d4 = idx & 15;
        *(float4*)&s_W1[a * 68 + d4 * 4] = *(const float4*)&W[a * 128 + 64 + d4 * 4];
    }
    __syncthreads();

    // ---- qp GEMM (f32x2) -> s_qp[a][q]; a<NF stored as e^{2*qp} ----
    {
        ull acc2[4][4];
#pragma unroll
        for (int i = 0; i < 4; i++)
#pragma unroll
            for (int j = 0; j < 4; j++) acc2[i][j] = 0ULL;
#pragma unroll
        for (int d4 = 0; d4 < 16; d4++) {
            ull wv[4][2];
#pragma unroll
            for (int j = 0; j < 4; j++) {
                float4 v = *(float4*)&s_W1[(tx + 16 * j) * 68 + d4 * 4];
                wv[j][0] = pk2(v.x, v.y); wv[j][1] = pk2(v.z, v.w);
            }
#pragma unroll
            for (int i = 0; i < 4; i++) {
                float4 v = *(float4*)&s_q[(ty * 4 + i) * 64 + d4 * 4];
                ull r0 = pk2(v.x, v.y), r1 = pk2(v.z, v.w);
#pragma unroll
                for (int j = 0; j < 4; j++) {
                    acc2[i][j] = ffma2(r0, wv[j][0], acc2[i][j]);
                    acc2[i][j] = ffma2(r1, wv[j][1], acc2[i][j]);
                }
            }
        }
#pragma unroll
        for (int i = 0; i < 4; i++)
#pragma unroll
            for (int j = 0; j < 4; j++) {
                float2 p = upk2(acc2[i][j]);
                float v = p.x + p.y + s_bias[tx + 16 * j];
                if (j < 2) v = exp2f(v * LOG2E2);          // Eq = e^{2*qp}, a<32
                s_qp[(tx + 16 * j) * 68 + ty * 4 + i] = v;
            }
    }
    __syncthreads();

    // ---- phase 2: stage x chunk [128][68] + Wk ----
#pragma unroll
    for (int i = 0; i < 8; i++) {
        int idx = tid + 256 * i; int k = idx >> 4, d4 = idx & 15;
        *(float4*)&s_xv[k * 68 + d4 * 4] =
            *(const float4*)&x[((size_t)b * KS_ + kc * KC_ + k) * KD_ + h * DH_ + d4 * 4];
    }
#pragma unroll
    for (int i = 0; i < 4; i++) {
        int idx = tid + 256 * i; int a = idx >> 4, d4 = idx & 15;
        *(float4*)&s_Wk[a * 68 + d4 * 4] = *(const float4*)&W[a * 128 + d4 * 4];
    }
    __syncthreads();

    // ---- kp GEMM (f32x2) -> s_kp[a][k]; a<NF stored as -e^{2*kp} ----
    {
        ull acc2[8][4];
#pragma unroll
        for (int i = 0; i < 8; i++)
#pragma unroll
            for (int j = 0; j < 4; j++) acc2[i][j] = 0ULL;
#pragma unroll
        for (int d4 = 0; d4 < 16; d4++) {
            ull wv[4][2];
#pragma unroll
            for (int j = 0; j < 4; j++) {
                float4 v = *(float4*)&s_Wk[(tx + 16 * j) * 68 + d4 * 4];
                wv[j][0] = pk2(v.x, v.y); wv[j][1] = pk2(v.z, v.w);
            }
#pragma unroll
            for (int i = 0; i < 8; i++) {
                float4 v = *(float4*)&s_xv[(ty * 8 + i) * 68 + d4 * 4];
                ull r0 = pk2(v.x, v.y), r1 = pk2(v.z, v.w);
#pragma unroll
                for (int j = 0; j < 4; j++) {
                    acc2[i][j] = ffma2(r0, wv[j][0], acc2[i][j]);
                    acc2[i][j] = ffma2(r1, wv[j][1], acc2[i][j]);
                }
            }
        }
#pragma unroll
        for (int i = 0; i < 8; i++)
#pragma unroll
            for (int j = 0; j < 4; j++) {
                float2 p = upk2(acc2[i][j]);
                float v = p.x + p.y;
                if (j < 2) v = -exp2f(v * LOG2E2);         // Ekn = -e^{2*kp}, a<32
                s_kp[(tx + 16 * j) * 132 + ty * 8 + i] = v;
            }
    }
    __syncthreads();

    // ---- phase 3: scores, FMA and MUFU paths INTERLEAVED per iteration ----
    //      q rows q0=ty*4 (4), k cols k0=tx*8 (8, as 4 packed pairs)
    const int q0 = ty * 4, k0 = tx * 8;
    const ull NEG1_2 = pk2(-1.f, -1.f);
    const ull ONE_2  = pk2(1.f, 1.f);

    // C = sum_{a<NF} w2[a], folded into accumulator init (FMA path identity)
    float C = 0.f;
#pragma unroll
    for (int a4 = 0; a4 < NF_ / 4; a4++) {
        float4 wv4 = *(float4*)&s_w2[a4 * 4];
        C += wv4.x + wv4.y + wv4.z + wv4.w;
    }

    ull acc2[4][4];
#pragma unroll
    for (int j = 0; j < 4; j++)
#pragma unroll
        for (int i = 0; i < 4; i++) acc2[j][i] = pk2(C, C);

#pragma unroll 2
    for (int a2 = 0; a2 < NF_; a2++) {
        // -- FMA path (a = a2): tanh = 1 - 2/(Eq*Ek + 1), Newton reciprocal --
        {
            float4 eq  = *(float4*)&s_qp[a2 * 68 + q0];
            float4 ekA = *(float4*)&s_kp[a2 * 132 + k0];
            float4 ekB = *(float4*)&s_kp[a2 * 132 + k0 + 4];
            ull ek[4] = {pk2(ekA.x, ekA.y), pk2(ekA.z, ekA.w),
                         pk2(ekB.x, ekB.y), pk2(ekB.z, ekB.w)};
            float w2m = -2.f * s_w2[a2];
            ull w22 = pk2(w2m, w2m);
            float eqs[4] = {eq.x, eq.y, eq.z, eq.w};
#pragma unroll
            for (int j = 0; j < 4; j++) {
                ull eqj = pk2(eqs[j], eqs[j]);
#pragma unroll
                for (int i = 0; i < 4; i++) {
                    ull nv = ffma2(eqj, ek[i], NEG1_2);     // -(Eq*Ek + 1)
                    ull r  = rcp_seed2(nv);
                    ull e  = ffma2(nv, r, ONE_2);           // 1 - v*r
                    r = ffma2(r, e, r);                      // r*(2 - v*r)
                    e = ffma2(nv, r, ONE_2);
                    r = ffma2(r, e, r);
                    acc2[j][i] = ffma2(w22, r, acc2[j][i]);  // += w2a*(1-2r)
                }
            }
        }
        // -- MUFU path (a = NF_+a2): direct tanh.approx, packed accumulate --
        {
            int a = NF_ + a2;
            float4 qv = *(float4*)&s_qp[a * 68 + q0];
            float4 kA = *(float4*)&s_kp[a * 132 + k0];
            float4 kB = *(float4*)&s_kp[a * 132 + k0 + 4];
            float w2a = s_w2[a];
            ull w2p = pk2(w2a, w2a);
            float qs[4] = {qv.x, qv.y, qv.z, qv.w};
            float ks[8] = {kA.x, kA.y, kA.z, kA.w, kB.x, kB.y, kB.z, kB.w};
#pragma unroll
            for (int j = 0; j < 4; j++) {
#pragma unroll
                for (int i = 0; i < 4; i++) {
                    float t0 = fast_tanh(qs[j] + ks[2 * i]);
                    float t1 = fast_tanh(qs[j] + ks[2 * i + 1]);
                    acc2[j][i] = ffma2(w2p, pk2(t0, t1), acc2[j][i]);
                }
            }
        }
    }

    // unpack packed accumulators
    float acc[4][8];
#pragma unroll
    for (int j = 0; j < 4; j++)
#pragma unroll
        for (int i = 0; i < 4; i++) {
            float2 f = upk2(acc2[j][i]);
            acc[j][2 * i] = f.x; acc[j][2 * i + 1] = f.y;
        }

    // ---- phase 4: exp (no max; |score| <= sum|w2|), rowsum, p to smem ----
    float rowsum[4];
    {
        unsigned char mk[8];
        const unsigned char* mrow = &mask[b * KS_ + kc * KC_ + k0];
#pragma unroll
        for (int i = 0; i < 8; i++) mk[i] = mrow[i];
#pragma unroll
        for (int j = 0; j < 4; j++) {
            float s = 0.f;
#pragma unroll
            for (int i = 0; i < 8; i++) {
                float p = mk[i] ? 0.f : __expf(acc[j][i]);
                acc[j][i] = p;
                s += p;
            }
#pragma unroll
            for (int o = 8; o; o >>= 1) s += __shfl_xor_sync(0xffffffffu, s, o);
            rowsum[j] = s;
        }
    }
    __syncthreads();   // phase-3 reads done before p overwrites Wk/qp region

#pragma unroll
    for (int j = 0; j < 4; j++) {
        *(float4*)&s_p[(q0 + j) * 132 + k0]     = make_float4(acc[j][0], acc[j][1], acc[j][2], acc[j][3]);
        *(float4*)&s_p[(q0 + j) * 132 + k0 + 4] = make_float4(acc[j][4], acc[j][5], acc[j][6], acc[j][7]);
    }
    if (tx == 0) {
#pragma unroll
        for (int j = 0; j < 4; j++)
            g_Sx[(bh * NC_ + kc) * QS_ + q0 + j] = rowsum[j];
    }
    __syncthreads();

    // ---- phase 5: partial out = p @ V (4q x 4d per thread) ----
    {
        const int txd = tid & 15, tyq = tid >> 4;
        const int d0 = txd * 4, q0b = tyq * 4;
        ull o2[4][2];
#pragma unroll
        for (int j = 0; j < 4; j++) { o2[j][0] = 0ULL; o2[j][1] = 0ULL; }

#pragma unroll 4
        for (int k = 0; k < KC_; k++) {
            float4 v = *(float4*)&s_xv[k * 68 + d0];
            ull v0 = pk2(v.x, v.y), v1 = pk2(v.z, v.w);
#pragma unroll
            for (int j = 0; j < 4; j++) {
                float p = s_p[(q0b + j) * 132 + k];
                ull p2 = pk2(p, p);
                o2[j][0] = ffma2(p2, v0, o2[j][0]);
                o2[j][1] = ffma2(p2, v1, o2[j][1]);
            }
        }
#pragma unroll
        for (int j = 0; j < 4; j++) {
            float2 a0 = upk2(o2[j][0]), a1 = upk2(o2[j][1]);
            *(float4*)&g_pout[(size_t)((bh * NC_ + kc) * QS_ + q0b + j) * DH_ + d0] =
                make_float4(a0.x, a0.y, a1.x, a1.y);
        }
    }
}

// ---------------- combine: merge 4 chunk partials, 1 float4 per thread ----------------
__global__ void __launch_bounds__(256) combine_kernel(float* __restrict__ out)
{
    const int idx = blockIdx.x * 256 + threadIdx.x;   // 0..1023 per bh
    const int bh = blockIdx.y;
    const int b = bh >> 3, h = bh & 7;
    const int q = idx >> 4, d0 = (idx & 15) * 4;

    float S = 0.f;
#pragma unroll
    for (int c = 0; c < NC_; c++) S += g_Sx[(bh * NC_ + c) * QS_ + q];
    float inv = 1.f / S;

    float4 a = make_float4(0.f, 0.f, 0.f, 0.f);
#pragma unroll
    for (int c = 0; c < NC_; c++) {
        float4 v = *(const float4*)&g_pout[(size_t)((bh * NC_ + c) * QS_ + q) * DH_ + d0];
        a.x += v.x; a.y += v.y; a.z += v.z; a.w += v.w;
    }
    a.x *= inv; a.y *= inv; a.z *= inv; a.w *= inv;

    *(float4*)&out[(size_t)(b * QS_ + q) * QD_ + h * DH_ + d0] = a;
}

// ---------------- launch ----------------
extern "C" void kernel_launch(void* const* d_in, const int* in_sizes, int n_in,
                              void* d_out, int out_size) {
    const float* x     = (const float*)d_in[0];
    const float* query = (const float*)d_in[1];
    const float* W     = (const float*)d_in[2];
    const float* bias  = (const float*)d_in[3];
    const float* w2    = (const float*)d_in[4];
    const unsigned char* mask = (const unsigned char*)d_in[5];
    float* out = (float*)d_out;

    cudaFuncSetAttribute(fused_kernel, cudaFuncAttributeMaxDynamicSharedMemorySize, SMF_BYTES);

    fused_kernel<<<dim3(NC_, H_, B_), 256, SMF_BYTES>>>(x, query, W, bias, w2, mask);
    combine_kernel<<<dim3(4, B_ * H_), 256>>>(out);
}

// round 13
// speedup vs baseline: 1.5025x; 1.0175x over previous
#include <cuda_runtime.h>

#define B_  8
#define H_  8
#define QS_ 64
#define KS_ 512
#define A_  64
#define DH_ 64
#define KC_ 128
#define NC_ 4
#define QD_ 512
#define KD_ 512
#define NF_ 38   // a in [0,NF): FMA-pipe 1-Newton reciprocal path; a in [NF,64): MUFU tanh
#define NM_ (A_ - NF_)   // 26 MUFU iterations

typedef unsigned long long ull;

__device__ float g_pout[B_*H_*NC_*QS_*DH_];   // 4 MB
__device__ float g_Sx[B_*H_*NC_*QS_];

__device__ __forceinline__ float fast_tanh(float v) {
    float y; asm("tanh.approx.f32 %0, %1;" : "=f"(y) : "f"(v)); return y;
}
__device__ __forceinline__ ull pk2(float x, float y) {
    ull r; asm("mov.b64 %0, {%1, %2};" : "=l"(r) : "f"(x), "f"(y)); return r;
}
__device__ __forceinline__ float2 upk2(ull v) {
    float2 r; asm("mov.b64 {%0, %1}, %2;" : "=f"(r.x), "=f"(r.y) : "l"(v)); return r;
}
__device__ __forceinline__ ull ffma2(ull a, ull b, ull c) {
    ull d; asm("fma.rn.f32x2 %0, %1, %2, %3;" : "=l"(d) : "l"(a), "l"(b), "l"(c)); return d;
}
__device__ __forceinline__ ull fadd2(ull a, ull b) {
    ull d; asm("add.rn.f32x2 %0, %1, %2;" : "=l"(d) : "l"(a), "l"(b)); return d;
}
// packed fast-reciprocal seed for 1/v given nv = -v (v >= 1):
// seed_int = 0x7EF311C3 - asint(v) = 0xFEF311C3 - asint(nv)  (mod 2^32)
__device__ __forceinline__ ull rcp_seed2(ull nv) {
    unsigned lo, hi;
    asm("mov.b64 {%0, %1}, %2;" : "=r"(lo), "=r"(hi) : "l"(nv));
    lo = 0xFEF311C3u - lo;
    hi = 0xFEF311C3u - hi;
    ull r; asm("mov.b64 %0, {%1, %2};" : "=l"(r) : "r"(lo), "r"(hi));
    return r;
}

// ---------------- smem layout (bytes) — R12 layout, verbatim ----------------
// s_xv @0 f32[128][68]; s_q @34816 f32[64][64] (stride 64, ends 51200);
// s_W1 @51200 f32[64][68]; s_kp @34816 (alias, f32[64][132]);
// s_Wk @68608; s_p @68608 (alias); s_qp @86016 f32[64][68];
// s_bias @103424; s_w2 @103680
#define SMF_BYTES 103936

__global__ void __launch_bounds__(256, 2) fused_kernel(
    const float* __restrict__ x, const float* __restrict__ query,
    const float* __restrict__ W, const float* __restrict__ bias,
    const float* __restrict__ w2, const unsigned char* __restrict__ mask)
{
    extern __shared__ char sm[];
    float* s_xv  = (float*)(sm);
    float* s_q   = (float*)(sm + 34816);
    float* s_W1  = (float*)(sm + 51200);
    float* s_kp  = (float*)(sm + 34816);
    float* s_Wk  = (float*)(sm + 68608);
    float* s_p   = (float*)(sm + 68608);
    float* s_qp  = (float*)(sm + 86016);
    float* s_bias= (float*)(sm + 103424);
    float* s_w2  = (float*)(sm + 103680);

    const int kc = blockIdx.x, h = blockIdx.y, b = blockIdx.z;
    const int tid = threadIdx.x;
    const int tx = tid & 15, ty = tid >> 4;
    const int bh = b * H_ + h;
    const float LOG2E2 = 2.885390082f;   // 2*log2(e)

    if (tid < 64) { s_bias[tid] = bias[tid]; s_w2[tid] = w2[tid]; }

    // ---- phase 1: stage query [64][64] (stride 64) + Wq ----
#pragma unroll
    for (int i = 0; i < 4; i++) {
        int idx = tid + 256 * i; int q = idx >> 4, d4 = idx & 15;
        *(float4*)&s_q[q * 64 + d4 * 4] =
            *(const float4*)&query[(size_t)(b * QS_ + q) * QD_ + h * DH_ + d4 * 4];
    }
#pragma unroll
    for (int i = 0; i < 4; i++) {
        int idx = tid + 256 * i; int a = idx >> 4, d4 = idx & 15;
        *(float4*)&s_W1[a * 68 + d4 * 4] = *(const float4*)&W[a * 128 + 64 + d4 * 4];
    }
    __syncthreads();

    // ---- qp GEMM (f32x2) -> s_qp[a][q]; a<NF stored as e^{2*qp} ----
    {
        ull acc2[4][4];
#pragma unroll
        for (int i = 0; i < 4; i++)
#pragma unroll
            for (int j = 0; j < 4; j++) acc2[i][j] = 0ULL;
#pragma unroll
        for (int d4 = 0; d4 < 16; d4++) {
            ull wv[4][2];
#pragma unroll
            for (int j = 0; j < 4; j++) {
                float4 v = *(float4*)&s_W1[(tx + 16 * j) * 68 + d4 * 4];
                wv[j][0] = pk2(v.x, v.y); wv[j][1] = pk2(v.z, v.w);
            }
#pragma unroll
            for (int i = 0; i < 4; i++) {
                float4 v = *(float4*)&s_q[(ty * 4 + i) * 64 + d4 * 4];
                ull r0 = pk2(v.x, v.y), r1 = pk2(v.z, v.w);
#pragma unroll
                for (int j = 0; j < 4; j++) {
                    acc2[i][j] = ffma2(r0, wv[j][0], acc2[i][j]);
                    acc2[i][j] = ffma2(r1, wv[j][1], acc2[i][j]);
                }
            }
        }
#pragma unroll
        for (int i = 0; i < 4; i++)
#pragma unroll
            for (int j = 0; j < 4; j++) {
                float2 p = upk2(acc2[i][j]);
                float v = p.x + p.y + s_bias[tx + 16 * j];
                if (tx + 16 * j < NF_) v = exp2f(v * LOG2E2);   // Eq = e^{2*qp}
                s_qp[(tx + 16 * j) * 68 + ty * 4 + i] = v;
            }
    }
    __syncthreads();

    // ---- phase 2: stage x chunk [128][68] + Wk ----
#pragma unroll
    for (int i = 0; i < 8; i++) {
        int idx = tid + 256 * i; int k = idx >> 4, d4 = idx & 15;
        *(float4*)&s_xv[k * 68 + d4 * 4] =
            *(const float4*)&x[((size_t)b * KS_ + kc * KC_ + k) * KD_ + h * DH_ + d4 * 4];
    }
#pragma unroll
    for (int i = 0; i < 4; i++) {
        int idx = tid + 256 * i; int a = idx >> 4, d4 = idx & 15;
        *(float4*)&s_Wk[a * 68 + d4 * 4] = *(const float4*)&W[a * 128 + d4 * 4];
    }
    __syncthreads();

    // ---- kp GEMM (f32x2) -> s_kp[a][k]; a<NF stored as -e^{2*kp} ----
    {
        ull acc2[8][4];
#pragma unroll
        for (int i = 0; i < 8; i++)
#pragma unroll
            for (int j = 0; j < 4; j++) acc2[i][j] = 0ULL;
#pragma unroll
        for (int d4 = 0; d4 < 16; d4++) {
            ull wv[4][2];
#pragma unroll
            for (int j = 0; j < 4; j++) {
                float4 v = *(float4*)&s_Wk[(tx + 16 * j) * 68 + d4 * 4];
                wv[j][0] = pk2(v.x, v.y); wv[j][1] = pk2(v.z, v.w);
            }
#pragma unroll
            for (int i = 0; i < 8; i++) {
                float4 v = *(float4*)&s_xv[(ty * 8 + i) * 68 + d4 * 4];
                ull r0 = pk2(v.x, v.y), r1 = pk2(v.z, v.w);
#pragma unroll
                for (int j = 0; j < 4; j++) {
                    acc2[i][j] = ffma2(r0, wv[j][0], acc2[i][j]);
                    acc2[i][j] = ffma2(r1, wv[j][1], acc2[i][j]);
                }
            }
        }
#pragma unroll
        for (int i = 0; i < 8; i++)
#pragma unroll
            for (int j = 0; j < 4; j++) {
                float2 p = upk2(acc2[i][j]);
                float v = p.x + p.y;
                if (tx + 16 * j < NF_) v = -exp2f(v * LOG2E2);  // Ekn = -e^{2*kp}
                s_kp[(tx + 16 * j) * 132 + ty * 8 + i] = v;
            }
    }
    __syncthreads();

    // ---- phase 3: scores; FMA (a<NF, 1-Newton) and MUFU (a>=NF) interleaved ----
    const int q0 = ty * 4, k0 = tx * 8;
    const ull NEG1_2 = pk2(-1.f, -1.f);
    const ull ONE_2  = pk2(1.f, 1.f);

    // C = sum_{a<NF} w2[a], folded into accumulator init (FMA path identity)
    float C = 0.f;
#pragma unroll
    for (int a = 0; a < NF_; a++) C += s_w2[a];

    ull acc2[4][4];
#pragma unroll
    for (int j = 0; j < 4; j++)
#pragma unroll
        for (int i = 0; i < 4; i++) acc2[j][i] = pk2(C, C);

#pragma unroll 2
    for (int a2 = 0; a2 < NF_; a2++) {
        // -- FMA path (a = a2): tanh = 1 - 2/(Eq*Ek + 1), ONE Newton step --
        {
            float4 eq  = *(float4*)&s_qp[a2 * 68 + q0];
            float4 ekA = *(float4*)&s_kp[a2 * 132 + k0];
            float4 ekB = *(float4*)&s_kp[a2 * 132 + k0 + 4];
            ull ek[4] = {pk2(ekA.x, ekA.y), pk2(ekA.z, ekA.w),
                         pk2(ekB.x, ekB.y), pk2(ekB.z, ekB.w)};
            float w2m = -2.f * s_w2[a2];
            ull w22 = pk2(w2m, w2m);
            float eqs[4] = {eq.x, eq.y, eq.z, eq.w};
#pragma unroll
            for (int j = 0; j < 4; j++) {
                ull eqj = pk2(eqs[j], eqs[j]);
#pragma unroll
                for (int i = 0; i < 4; i++) {
                    ull nv = ffma2(eqj, ek[i], NEG1_2);     // -(Eq*Ek + 1)
                    ull r  = rcp_seed2(nv);
                    ull e  = ffma2(nv, r, ONE_2);           // 1 - v*r
                    r = ffma2(r, e, r);                      // r*(2 - v*r)
                    acc2[j][i] = ffma2(w22, r, acc2[j][i]);  // += w2a*(1-2r)
                }
            }
        }
        // -- MUFU path (a = NF_+a2, only NM_ of them): packed args + tanh.approx --
        if (a2 < NM_) {
            int a = NF_ + a2;
            float4 qv = *(float4*)&s_qp[a * 68 + q0];
            float4 kA = *(float4*)&s_kp[a * 132 + k0];
            float4 kB = *(float4*)&s_kp[a * 132 + k0 + 4];
            float w2a = s_w2[a];
            ull w2p = pk2(w2a, w2a);
            ull kp2v[4] = {pk2(kA.x, kA.y), pk2(kA.z, kA.w),
                           pk2(kB.x, kB.y), pk2(kB.z, kB.w)};
            float qs[4] = {qv.x, qv.y, qv.z, qv.w};
#pragma unroll
            for (int j = 0; j < 4; j++) {
                ull qj2 = pk2(qs[j], qs[j]);
#pragma unroll
                for (int i = 0; i < 4; i++) {
                    float2 arg = upk2(fadd2(qj2, kp2v[i]));   // packed q+k
                    float t0 = fast_tanh(arg.x);
                    float t1 = fast_tanh(arg.y);
                    acc2[j][i] = ffma2(w2p, pk2(t0, t1), acc2[j][i]);
                }
            }
        }
    }

    // unpack packed accumulators
    float acc[4][8];
#pragma unroll
    for (int j = 0; j < 4; j++)
#pragma unroll
        for (int i = 0; i < 4; i++) {
            float2 f = upk2(acc2[j][i]);
            acc[j][2 * i] = f.x; acc[j][2 * i + 1] = f.y;
        }

    // ---- phase 4: exp (no max; |score| <= sum|w2|), rowsum, p to smem ----
    float rowsum[4];
    {
        unsigned char mk[8];
        const unsigned char* mrow = &mask[b * KS_ + kc * KC_ + k0];
#pragma unroll
        for (int i = 0; i < 8; i++) mk[i] = mrow[i];
#pragma unroll
        for (int j = 0; j < 4; j++) {
            float s = 0.f;
#pragma unroll
            for (int i = 0; i < 8; i++) {
                float p = mk[i] ? 0.f : __expf(acc[j][i]);
                acc[j][i] = p;
                s += p;
            }
#pragma unroll
            for (int o = 8; o; o >>= 1) s += __shfl_xor_sync(0xffffffffu, s, o);
            rowsum[j] = s;
        }
    }
    __syncthreads();   // phase-3 reads done before p overwrites Wk/qp region

#pragma unroll
    for (int j = 0; j < 4; j++) {
        *(float4*)&s_p[(q0 + j) * 132 + k0]     = make_float4(acc[j][0], acc[j][1], acc[j][2], acc[j][3]);
        *(float4*)&s_p[(q0 + j) * 132 + k0 + 4] = make_float4(acc[j][4], acc[j][5], acc[j][6], acc[j][7]);
    }
    if (tx == 0) {
#pragma unroll
        for (int j = 0; j < 4; j++)
            g_Sx[(bh * NC_ + kc) * QS_ + q0 + j] = rowsum[j];
    }
    __syncthreads();

    // ---- phase 5: partial out = p @ V (4q x 4d per thread) ----
    {
        const int txd = tid & 15, tyq = tid >> 4;
        const int d0 = txd * 4, q0b = tyq * 4;
        ull o2[4][2];
#pragma unroll
        for (int j = 0; j < 4; j++) { o2[j][0] = 0ULL; o2[j][1] = 0ULL; }

#pragma unroll 4
        for (int k = 0; k < KC_; k++) {
            float4 v = *(float4*)&s_xv[k * 68 + d0];
            ull v0 = pk2(v.x, v.y), v1 = pk2(v.z, v.w);
#pragma unroll
            for (int j = 0; j < 4; j++) {
                float p = s_p[(q0b + j) * 132 + k];
                ull p2 = pk2(p, p);
                o2[j][0] = ffma2(p2, v0, o2[j][0]);
                o2[j][1] = ffma2(p2, v1, o2[j][1]);
            }
        }
#pragma unroll
        for (int j = 0; j < 4; j++) {
            float2 a0 = upk2(o2[j][0]), a1 = upk2(o2[j][1]);
            *(float4*)&g_pout[(size_t)((bh * NC_ + kc) * QS_ + q0b + j) * DH_ + d0] =
                make_float4(a0.x, a0.y, a1.x, a1.y);
        }
    }
}

// ---------------- combine: merge 4 chunk partials, 1 float4 per thread ----------------
__global__ void __launch_bounds__(256) combine_kernel(float* __restrict__ out)
{
    const int idx = blockIdx.x * 256 + threadIdx.x;   // 0..1023 per bh
    const int bh = blockIdx.y;
    const int b = bh >> 3, h = bh & 7;
    const int q = idx >> 4, d0 = (idx & 15) * 4;

    float S = 0.f;
#pragma unroll
    for (int c = 0; c < NC_; c++) S += g_Sx[(bh * NC_ + c) * QS_ + q];
    float inv = 1.f / S;

    float4 a = make_float4(0.f, 0.f, 0.f, 0.f);
#pragma unroll
    for (int c = 0; c < NC_; c++) {
        float4 v = *(const float4*)&g_pout[(size_t)((bh * NC_ + c) * QS_ + q) * DH_ + d0];
        a.x += v.x; a.y += v.y; a.z += v.z; a.w += v.w;
    }
    a.x *= inv; a.y *= inv; a.z *= inv; a.w *= inv;

    *(float4*)&out[(size_t)(b * QS_ + q) * QD_ + h * DH_ + d0] = a;
}

// ---------------- launch ----------------
extern "C" void kernel_launch(void* const* d_in, const int* in_sizes, int n_in,
                              void* d_out, int out_size) {
    const float* x     = (const float*)d_in[0];
    const float* query = (const float*)d_in[1];
    const float* W     = (const float*)d_in[2];
    const float* bias  = (const float*)d_in[3];
    const float* w2    = (const float*)d_in[4];
    const unsigned char* mask = (const unsigned char*)d_in[5];
    float* out = (float*)d_out;

    cudaFuncSetAttribute(fused_kernel, cudaFuncAttributeMaxDynamicSharedMemorySize, SMF_BYTES);

    fused_kernel<<<dim3(NC_, H_, B_), 256, SMF_BYTES>>>(x, query, W, bias, w2, mask);
    combine_kernel<<<dim3(4, B_ * H_), 256>>>(out);
}